// round 14
// baseline (speedup 1.0000x reference)
#include <cuda_runtime.h>
#include <cuda_fp16.h>
#include <cstdint>

#define D        64
#define MT       128         // x rows per CTA
#define NC       128         // codes per chunk (64B/code -> 8KB slot)
#define TPB      160         // 4 consumer warps + 1 producer warp
#define MAXM     4096
#define RING     3

__device__ __align__(16) uint8_t g_codes_f8[MAXM * D];
__device__ __align__(16) float   g_c2f[MAXM];    // -0.5 * ||c_quantized||^2

static __device__ __forceinline__ uint32_t su32(const void* p) {
    uint32_t a;
    asm("{ .reg .u64 t; cvta.to.shared.u64 t, %1; cvt.u32.u64 %0, t; }" : "=r"(a) : "l"(p));
    return a;
}
// pack 2 f32 -> 2 e4m3 bytes
static __device__ __forceinline__ uint16_t pk8(float lo, float hi) {
    uint16_t u;
    asm("cvt.rn.satfinite.e4m3x2.f32 %0, %1, %2;" : "=h"(u) : "f"(hi), "f"(lo));
    return u;
}
// dequant 2 e4m3 bytes -> float2 (exact via f16)
static __device__ __forceinline__ float2 dq8(uint16_t u) {
    uint32_t h2;
    asm("cvt.rn.f16x2.e4m3x2 %0, %1;" : "=r"(h2) : "h"(u));
    __half2 hh = *reinterpret_cast<__half2*>(&h2);
    return __half22float2(hh);
}

#define LDSM4(r0, r1, r2, r3, addr)                                                   \
    asm volatile("ldmatrix.sync.aligned.m8n8.x4.shared.b16 {%0,%1,%2,%3}, [%4];"      \
                 : "=r"(r0), "=r"(r1), "=r"(r2), "=r"(r3) : "r"(addr))

// fp8 MMA, fp32 accum, acc in-place
#define MMA_FP8(dd, a, b0, b1)                                                        \
    asm volatile("mma.sync.aligned.m16n8k32.row.col.f32.e4m3.e4m3.f32 "               \
                 "{%0,%1,%2,%3},{%4,%5,%6,%7},{%8,%9},{%0,%1,%2,%3};"                 \
                 : "+f"((dd)[0]), "+f"((dd)[1]), "+f"((dd)[2]), "+f"((dd)[3])         \
                 : "r"((a)[0]), "r"((a)[1]), "r"((a)[2]), "r"((a)[3]),                \
                   "r"(b0), "r"(b1))

#define CPASYNC16(saddr, gptr)                                                        \
    asm volatile("cp.async.cg.shared.global [%0], [%1], 16;" :: "r"(saddr), "l"(gptr))
#define CPWAIT0()  asm volatile("cp.async.wait_group 0;")
#define CPASYNC_MBAR_ARRIVE(mbar)                                                     \
    asm volatile("cp.async.mbarrier.arrive.noinc.shared.b64 [%0];" :: "r"(mbar) : "memory")
#define MBARRIER_INIT(mbar, cnt)                                                      \
    asm volatile("mbarrier.init.shared.b64 [%0], %1;" :: "r"(mbar), "r"(cnt) : "memory")
#define MBARRIER_ARRIVE(mbar)                                                         \
    asm volatile("mbarrier.arrive.shared.b64 _, [%0];" :: "r"(mbar) : "memory")
#define MBARRIER_WAIT_PARITY(mbar, parity) do {                                       \
    uint32_t _m = (mbar), _p = (parity), _done;                                       \
    asm volatile("{\n\t.reg .pred p;\n\t"                                             \
        "mbarrier.try_wait.parity.acquire.cta.shared::cta.b64 p, [%1], %2;\n\t"       \
        "selp.b32 %0, 1, 0, p;\n\t}"                                                  \
        : "=r"(_done) : "r"(_m), "r"(_p) : "memory");                                 \
    if (!_done) {                                                                     \
        asm volatile("{\n\t.reg .pred P1;\n\t"                                        \
            "WL_%=:\n\t"                                                              \
            "mbarrier.try_wait.parity.acquire.cta.shared::cta.b64 P1, [%0], %1, 0x989680;\n\t" \
            "@P1 bra.uni WD_%=;\n\t"                                                  \
            "bra.uni WL_%=;\n\t"                                                      \
            "WD_%=:\n\t}" :: "r"(_m), "r"(_p) : "memory");                            \
    }                                                                                 \
} while (0)

// 64B-row swizzle: row r, 16B-chunk kb (0..3)
static __device__ __forceinline__ uint32_t sw64(int row, int kb) {
    return (uint32_t)row * 64u + (uint32_t)((kb ^ ((row >> 1) & 3)) << 4);
}

// ---------------- prep: codes -> e4m3 + fp32(-||c~||^2/2) ----------------
__global__ void prep_kernel(const float* __restrict__ codes, int M) {
    int gid = blockIdx.x * blockDim.x + threadIdx.x;
    int m = gid >> 4, seg = gid & 15;
    if (m >= M) return;
    float4 v = __ldg(reinterpret_cast<const float4*>(codes + (size_t)m * D) + seg);
    uint16_t pa = pk8(v.x, v.y), pb = pk8(v.z, v.w);
    float2 da = dq8(pa), db = dq8(pb);
    float s = da.x * da.x + da.y * da.y + db.x * db.x + db.y * db.y;
    s += __shfl_xor_sync(0xFFFFFFFFu, s, 1);
    s += __shfl_xor_sync(0xFFFFFFFFu, s, 2);
    s += __shfl_xor_sync(0xFFFFFFFFu, s, 4);
    s += __shfl_xor_sync(0xFFFFFFFFu, s, 8);
    reinterpret_cast<uint32_t*>(g_codes_f8)[m * 16 + seg] = (uint32_t)pa | ((uint32_t)pb << 16);
    if (seg == 0) g_c2f[m] = -0.5f * s;
}

// ---------------- main kernel ----------------
__global__ __launch_bounds__(TPB, 4) void nn_mma_kernel(
    const float* __restrict__ x, const float* __restrict__ codes,
    float* __restrict__ out, int M)
{
    __shared__ __align__(128) unsigned char smRing[RING * NC * 64];  // 24KB
    __shared__ __align__(128) unsigned char smA[MT * 64];            // 8KB
    __shared__ __align__(8)   unsigned char smBar[2 * RING * 8];
    __shared__ float sD2[MT];

    const int t = threadIdx.x;
    const int L = t & 31;
    const int w = t >> 5;
    const int CHUNKS = M / NC;        // 32

    const uint32_t ringB  = su32(smRing);
    const uint32_t sAb    = su32(smA);
    const uint32_t fullB  = su32(smBar);
    const uint32_t emptyB = fullB + RING * 8;

    if (t == 0) {
#pragma unroll
        for (int s = 0; s < RING; s++) {
            MBARRIER_INIT(fullB  + s * 8, 32);
            MBARRIER_INIT(emptyB + s * 8, 128);
        }
    }

    // ---- consumer threads: quantize x row t -> e4m3 into smA (swizzled) ----
    float x2 = 0.f;
    if (t < MT) {
        const float4* xr = reinterpret_cast<const float4*>(
            x + ((size_t)blockIdx.x * MT + t) * D);
#pragma unroll
        for (int kb = 0; kb < 4; kb++) {
            uint32_t q[4];
#pragma unroll
            for (int j = 0; j < 4; j++) {
                float4 v = xr[4 * kb + j];
                uint16_t pa = pk8(v.x, v.y), pb = pk8(v.z, v.w);
                float2 da = dq8(pa), db = dq8(pb);
                x2 += da.x * da.x + da.y * da.y + db.x * db.x + db.y * db.y;
                q[j] = (uint32_t)pa | ((uint32_t)pb << 16);
            }
            *reinterpret_cast<uint4*>(smA + sw64(t, kb) - (sAb - su32(smA)) + 0) =
                make_uint4(q[0], q[1], q[2], q[3]);
        }
    }
    __syncthreads();      // A staged + mbarriers initialized

    if (w == 4) {
        // ================= producer warp =================
        int es = 0, ep = 1;
#pragma unroll 1
        for (int ch = 0; ch < CHUNKS; ch++) {
            MBARRIER_WAIT_PARITY(emptyB + es * 8, ep);
            const uint32_t dst = ringB + (uint32_t)es * (NC * 64);
            const char* src = reinterpret_cast<const char*>(g_codes_f8) + (size_t)ch * (NC * 64);
#pragma unroll
            for (int i = 0; i < 16; i++) {
                int idx = L + i * 32;          // 512 x 16B = 8KB
                int n = idx >> 2, kb = idx & 3;
                CPASYNC16(dst + sw64(n, kb), src + idx * 16);
            }
            CPASYNC_MBAR_ARRIVE(fullB + es * 8);
            if (++es == RING) { es = 0; ep ^= 1; }
        }
        CPWAIT0();
        return;
    }

    // ================= consumer warps (0-3) =================
    // A fragments: warp w owns rows w*32..w*32+31; [mt][kstep][4]
    uint32_t Af[2][2][4];
    const int mbw = w * 32;
#pragma unroll
    for (int mt = 0; mt < 2; mt++)
#pragma unroll
        for (int ks = 0; ks < 2; ks++) {
            int r  = mbw + mt * 16 + (L & 15);
            int kb = 2 * ks + (L >> 4);
            LDSM4(Af[mt][ks][0], Af[mt][ks][1], Af[mt][ks][2], Af[mt][ks][3],
                  sAb + sw64(r, kb));
        }

    const int g  = L >> 2;
    const int tc = L & 3;
    const int rB = L & 7;        // B row within ntile
    const int kB = L >> 3;       // B 16B-chunk

    float kmax[2][2] = {{-3.4e38f, -3.4e38f}, {-3.4e38f, -3.4e38f}};

    int fs = 0, fp = 0;
#pragma unroll 1
    for (int ch = 0; ch < CHUNKS; ch++) {
        const int cb = ch * NC;

        // hoisted: -c^2/2 for this lane's 2 cols of each of 16 ntiles
        float2 c2v[16];
#pragma unroll
        for (int nt = 0; nt < 16; nt++)
            c2v[nt] = __ldg(reinterpret_cast<const float2*>(g_c2f + cb + nt * 8 + tc * 2));

        MBARRIER_WAIT_PARITY(fullB + fs * 8, fp);
        const uint32_t sBc = ringB + (uint32_t)fs * (NC * 64);

#pragma unroll
        for (int pp = 0; pp < 8; pp++) {
            const int nt0 = 2 * pp, nt1 = 2 * pp + 1;
            uint32_t b0[4], b1[4];
            LDSM4(b0[0], b0[1], b0[2], b0[3], sBc + sw64(nt0 * 8 + rB, kB));
            LDSM4(b1[0], b1[1], b1[2], b1[3], sBc + sw64(nt1 * 8 + rB, kB));

            float a00[4] = {c2v[nt0].x, c2v[nt0].y, c2v[nt0].x, c2v[nt0].y};
            float a01[4] = {c2v[nt0].x, c2v[nt0].y, c2v[nt0].x, c2v[nt0].y};
            float a10[4] = {c2v[nt1].x, c2v[nt1].y, c2v[nt1].x, c2v[nt1].y};
            float a11[4] = {c2v[nt1].x, c2v[nt1].y, c2v[nt1].x, c2v[nt1].y};

            MMA_FP8(a00, Af[0][0], b0[0], b0[1]);
            MMA_FP8(a01, Af[1][0], b0[0], b0[1]);
            MMA_FP8(a10, Af[0][0], b1[0], b1[1]);
            MMA_FP8(a11, Af[1][0], b1[0], b1[1]);
            MMA_FP8(a00, Af[0][1], b0[2], b0[3]);
            MMA_FP8(a01, Af[1][1], b0[2], b0[3]);
            MMA_FP8(a10, Af[0][1], b1[2], b1[3]);
            MMA_FP8(a11, Af[1][1], b1[2], b1[3]);

            kmax[0][0] = fmaxf(kmax[0][0], fmaxf(fmaxf(a00[0], a00[1]), fmaxf(a10[0], a10[1])));
            kmax[0][1] = fmaxf(kmax[0][1], fmaxf(fmaxf(a00[2], a00[3]), fmaxf(a10[2], a10[3])));
            kmax[1][0] = fmaxf(kmax[1][0], fmaxf(fmaxf(a01[0], a01[1]), fmaxf(a11[0], a11[1])));
            kmax[1][1] = fmaxf(kmax[1][1], fmaxf(fmaxf(a01[2], a01[3]), fmaxf(a11[2], a11[3])));
        }

        MBARRIER_ARRIVE(emptyB + fs * 8);
        if (++fs == RING) { fs = 0; fp ^= 1; }
    }

    // ---- reduce across 4 tc lanes; publish approx min d^2 ----
#pragma unroll
    for (int mt = 0; mt < 2; mt++)
#pragma unroll
        for (int h = 0; h < 2; h++) {
            float v = kmax[mt][h];
            v = fmaxf(v, __shfl_xor_sync(0xFFFFFFFFu, v, 1));
            v = fmaxf(v, __shfl_xor_sync(0xFFFFFFFFu, v, 2));
            float x2row = __shfl_sync(0xFFFFFFFFu, x2, mt * 16 + h * 8 + g);
            if (tc == 0)
                sD2[mbw + mt * 16 + h * 8 + g] = fmaf(v, -2.f, x2row);  // min ||x~-c~||^2
        }
    asm volatile("bar.sync 1, 128;" ::: "memory");   // consumer threads only

    // ---- fused finalize: warp-cooperative exact rescue for flagged rows ----
    {
        float d2a = sD2[t];
        float res = -1.0f;
        unsigned need = __ballot_sync(0xFFFFFFFFu, d2a <= 16.0f);   // ~10 sigma margin
        while (need) {
            int lr = __ffs(need) - 1;
            need &= need - 1;
            const int rrow = blockIdx.x * MT + (w << 5) + lr;
            const float* xr = x + (size_t)rrow * D;
            float best = 3.4e38f;
            int   bi = 0x7FFFFFFF;
#pragma unroll 1
            for (int m = L; m < M; m += 32) {
                const float* c = codes + (size_t)m * D;
                float s = 0.f;
#pragma unroll 8
                for (int i = 0; i < D; i++) {
                    float dd = __ldg(xr + i) - __ldg(c + i);
                    s = fmaf(dd, dd, s);
                }
                if (s < best) { best = s; bi = m; }
            }
#pragma unroll
            for (int off = 16; off; off >>= 1) {
                float ob = __shfl_xor_sync(0xFFFFFFFFu, best, off);
                int   oi = __shfl_xor_sync(0xFFFFFFFFu, bi, off);
                if (ob < best || (ob == best && oi < bi)) { best = ob; bi = oi; }
            }
            if (L == lr) res = (best <= 0.1f) ? (float)bi : -1.0f;
        }
        out[(size_t)blockIdx.x * MT + t] = res;
    }
}

extern "C" void kernel_launch(void* const* d_in, const int* in_sizes, int n_in,
                              void* d_out, int out_size) {
    const float* x     = (const float*)d_in[0];
    const float* codes = (const float*)d_in[1];
    float*       out   = (float*)d_out;

    const int M     = in_sizes[1] / D;     // 4096
    const int nRows = in_sizes[0] / D;     // 65536

    prep_kernel<<<(M * 16) / 256, 256>>>(codes, M);
    nn_mma_kernel<<<nRows / MT, TPB>>>(x, codes, out, M);
}

// round 15
// speedup vs baseline: 1.3466x; 1.3466x over previous
#include <cuda_runtime.h>
#include <cuda_fp16.h>
#include <cstdint>

#define D        64
#define MT       128         // x rows per CTA
#define NC       128         // codes per chunk (16KB slot)
#define TPB      160         // 4 consumer warps + 1 producer warp
#define MAXM     4096
#define RING     2

__device__ __align__(16) __half g_codes_f16[MAXM * D];
__device__ __align__(16) __half g_c2h[MAXM];          // fp16(-||c||^2 / 2)

static __device__ __forceinline__ uint32_t su32(const void* p) {
    uint32_t a;
    asm("{ .reg .u64 t; cvta.to.shared.u64 t, %1; cvt.u32.u64 %0, t; }" : "=r"(a) : "l"(p));
    return a;
}
static __device__ __forceinline__ uint32_t h2u(__half2 h) {
    return *reinterpret_cast<uint32_t*>(&h);
}
static __device__ __forceinline__ __half2 u2h(uint32_t u) {
    return *reinterpret_cast<__half2*>(&u);
}

#define LDSM4(r0, r1, r2, r3, addr)                                                   \
    asm volatile("ldmatrix.sync.aligned.m8n8.x4.shared.b16 {%0,%1,%2,%3}, [%4];"      \
                 : "=r"(r0), "=r"(r1), "=r"(r2), "=r"(r3) : "r"(addr))

#define MMA16816H(c0, c1, a, b0, b1)                                                  \
    asm volatile("mma.sync.aligned.m16n8k16.row.col.f16.f16.f16.f16 "                 \
                 "{%0,%1},{%2,%3,%4,%5},{%6,%7},{%0,%1};"                             \
                 : "+r"(c0), "+r"(c1)                                                 \
                 : "r"((a)[0]), "r"((a)[1]), "r"((a)[2]), "r"((a)[3]),                \
                   "r"(b0), "r"(b1))

#define CPASYNC16(saddr, gptr)                                                        \
    asm volatile("cp.async.cg.shared.global [%0], [%1], 16;" :: "r"(saddr), "l"(gptr))
#define CPWAIT0()  asm volatile("cp.async.wait_group 0;")
#define CPASYNC_MBAR_ARRIVE(mbar)                                                     \
    asm volatile("cp.async.mbarrier.arrive.noinc.shared.b64 [%0];" :: "r"(mbar) : "memory")

#define MBARRIER_INIT(mbar, cnt)                                                      \
    asm volatile("mbarrier.init.shared.b64 [%0], %1;" :: "r"(mbar), "r"(cnt) : "memory")
#define MBARRIER_ARRIVE(mbar)                                                         \
    asm volatile("mbarrier.arrive.shared.b64 _, [%0];" :: "r"(mbar) : "memory")

#define MBARRIER_WAIT_PARITY(mbar, parity) do {                                       \
    uint32_t _m = (mbar), _p = (parity), _done;                                       \
    asm volatile("{\n\t.reg .pred p;\n\t"                                             \
        "mbarrier.try_wait.parity.acquire.cta.shared::cta.b64 p, [%1], %2;\n\t"       \
        "selp.b32 %0, 1, 0, p;\n\t}"                                                  \
        : "=r"(_done) : "r"(_m), "r"(_p) : "memory");                                 \
    if (!_done) {                                                                     \
        asm volatile("{\n\t.reg .pred P1;\n\t"                                        \
            "WL_%=:\n\t"                                                              \
            "mbarrier.try_wait.parity.acquire.cta.shared::cta.b64 P1, [%0], %1, 0x989680;\n\t" \
            "@P1 bra.uni WD_%=;\n\t"                                                  \
            "bra.uni WL_%=;\n\t"                                                      \
            "WD_%=:\n\t}" :: "r"(_m), "r"(_p) : "memory");                            \
    }                                                                                 \
} while (0)

// ---------------- prep: 16 threads per code row ----------------
__global__ void prep_kernel(const float* __restrict__ codes, int M) {
    int gid = blockIdx.x * blockDim.x + threadIdx.x;
    int m = gid >> 4, seg = gid & 15;
    if (m >= M) return;
    float4 v = __ldg(reinterpret_cast<const float4*>(codes + (size_t)m * D) + seg);
    float s = v.x * v.x + v.y * v.y + v.z * v.z + v.w * v.w;
    s += __shfl_xor_sync(0xFFFFFFFFu, s, 1);
    s += __shfl_xor_sync(0xFFFFFFFFu, s, 2);
    s += __shfl_xor_sync(0xFFFFFFFFu, s, 4);
    s += __shfl_xor_sync(0xFFFFFFFFu, s, 8);
    uint2 u;
    u.x = h2u(__floats2half2_rn(v.x, v.y));
    u.y = h2u(__floats2half2_rn(v.z, v.w));
    reinterpret_cast<uint2*>(g_codes_f16 + (size_t)m * D)[seg] = u;
    if (seg == 0) g_c2h[m] = __float2half_rn(-0.5f * s);   // acc-init form
}

// dynamic smem layout
#define OFF_RING   0                       // RING x 16384
#define OFF_A      (RING * 16384)          // 16384
#define OFF_FULL   (OFF_A + 16384)         // RING x 8
#define OFF_EMPTY  (OFF_FULL + RING * 8)   // RING x 8
#define OFF_D2     (OFF_EMPTY + RING * 8)  // 512
#define SMEM_TOTAL (OFF_D2 + 512)

__global__ void __launch_bounds__(TPB, 4) nn_mma_kernel(
    const float* __restrict__ x, const float* __restrict__ codes,
    float* __restrict__ out, int M)
{
    extern __shared__ __align__(128) unsigned char sm[];
    float* sD2 = reinterpret_cast<float*>(sm + OFF_D2);

    const int t = threadIdx.x;
    const int L = t & 31;
    const int w = t >> 5;
    const int CHUNKS = M / NC;        // 32

    // stagger: each CTA walks chunks starting at a different point
    const int s0 = (blockIdx.x * 7) & (CHUNKS - 1);

    const uint32_t sb = su32(sm);
    const uint32_t ringB  = sb + OFF_RING;
    const uint32_t fullB  = sb + OFF_FULL;
    const uint32_t emptyB = sb + OFF_EMPTY;

    if (t == 0) {
#pragma unroll
        for (int s = 0; s < RING; s++) {
            MBARRIER_INIT(fullB  + s * 8, 32);    // producer lanes arrive-on-complete
            MBARRIER_INIT(emptyB + s * 8, 128);   // consumer threads arrive
        }
    }

    // ---- consumer threads stage x rows into A; x2 in a register ----
    float x2 = 0.f;
    if (t < MT) {
        const float4* xr = reinterpret_cast<const float4*>(
            x + ((size_t)blockIdx.x * MT + t) * D);
        unsigned char* sA = sm + OFF_A;
#pragma unroll
        for (int i = 0; i < 8; i++) {
            float4 f0 = xr[2 * i], f1 = xr[2 * i + 1];
            x2 += f0.x * f0.x + f0.y * f0.y + f0.z * f0.z + f0.w * f0.w;
            x2 += f1.x * f1.x + f1.y * f1.y + f1.z * f1.z + f1.w * f1.w;
            uint4 u;
            u.x = h2u(__floats2half2_rn(f0.x, f0.y));
            u.y = h2u(__floats2half2_rn(f0.z, f0.w));
            u.z = h2u(__floats2half2_rn(f1.x, f1.y));
            u.w = h2u(__floats2half2_rn(f1.z, f1.w));
            *reinterpret_cast<uint4*>(sA + t * 128 + ((i ^ (t & 7)) << 4)) = u;
        }
    }
    __syncthreads();      // A staged + mbarriers initialized

    if (w == 4) {
        // ================= producer warp =================
        int es = 0, ep = 1;       // empty cursor (phase 1: first RING waits pass)
#pragma unroll 1
        for (int it = 0; it < CHUNKS; it++) {
            const int ch = (s0 + it) & (CHUNKS - 1);
            MBARRIER_WAIT_PARITY(emptyB + es * 8, ep);
            const uint32_t dst = ringB + (uint32_t)es * 16384u;
            const char* src = reinterpret_cast<const char*>(g_codes_f16) + (size_t)ch * 16384;
#pragma unroll
            for (int i = 0; i < 32; i++) {
                int idx = L + i * 32;
                int n = idx >> 3, kb = idx & 7;
                CPASYNC16(dst + n * 128 + ((kb ^ (n & 7)) << 4), src + idx * 16);
            }
            CPASYNC_MBAR_ARRIVE(fullB + es * 8);
            if (++es == RING) { es = 0; ep ^= 1; }
        }
        CPWAIT0();
        return;                   // producer done
    }

    // ================= consumer warps (0-3) =================
    uint32_t Af[2][4][4];
    const uint32_t sAb = sb + OFF_A;
    const int mbw = w * 32;
#pragma unroll
    for (int mt = 0; mt < 2; mt++)
#pragma unroll
        for (int k = 0; k < 4; k++) {
            int r  = mbw + mt * 16 + (L & 15);
            int kb = 2 * k + (L >> 4);
            uint32_t addr = sAb + r * 128 + ((kb ^ (r & 7)) << 4);
            LDSM4(Af[mt][k][0], Af[mt][k][1], Af[mt][k][2], Af[mt][k][3], addr);
        }

    const int g   = L >> 2;
    const int tc  = L & 3;
    const int rrb = (L & 7) + ((L >> 4) << 3);
    const int kbb = (L >> 3) & 1;

    __half2 kmax[2][2];
#pragma unroll
    for (int a = 0; a < 2; a++)
#pragma unroll
        for (int b = 0; b < 2; b++) kmax[a][b] = __floats2half2_rn(-65504.f, -65504.f);

    int fs = 0, fp = 0;           // full cursor
#pragma unroll 1
    for (int it = 0; it < CHUNKS; it++) {
        const int ch = (s0 + it) & (CHUNKS - 1);
        const int cb = ch * NC;

        // ---- hoisted off the critical path: c2 for all 16 n-tiles ----
        uint32_t c2v[8][2];
#pragma unroll
        for (int p = 0; p < 8; p++) {
            c2v[p][0] = __ldg(reinterpret_cast<const uint32_t*>(g_c2h + cb + (2 * p) * 8 + tc * 2));
            c2v[p][1] = __ldg(reinterpret_cast<const uint32_t*>(g_c2h + cb + (2 * p + 1) * 8 + tc * 2));
        }

        MBARRIER_WAIT_PARITY(fullB + fs * 8, fp);
        const uint32_t sBc = ringB + (uint32_t)fs * 16384u;

#pragma unroll
        for (int pp = 0; pp < 4; pp++) {        // p = 2pp, 2pp+1
            uint32_t acc[2][2][2][2];
#pragma unroll
            for (int pi = 0; pi < 2; pi++)
#pragma unroll
                for (int mt = 0; mt < 2; mt++)
#pragma unroll
                    for (int nt = 0; nt < 2; nt++) {
                        acc[pi][mt][nt][0] = c2v[2 * pp + pi][nt];
                        acc[pi][mt][nt][1] = c2v[2 * pp + pi][nt];
                    }

            const int r0 = (2 * pp) * 16 + rrb;
            const int r1 = (2 * pp + 1) * 16 + rrb;

            uint32_t f[2][8];
            {
                const int kb = kbb;
                LDSM4(f[0][0], f[0][1], f[0][2], f[0][3], sBc + r0 * 128 + ((kb ^ (r0 & 7)) << 4));
                LDSM4(f[0][4], f[0][5], f[0][6], f[0][7], sBc + r1 * 128 + ((kb ^ (r1 & 7)) << 4));
            }
#pragma unroll
            for (int k = 0; k < 4; k++) {
                if (k < 3) {
                    const int kb = 2 * (k + 1) + kbb;
                    LDSM4(f[(k + 1) & 1][0], f[(k + 1) & 1][1], f[(k + 1) & 1][2], f[(k + 1) & 1][3],
                          sBc + r0 * 128 + ((kb ^ (r0 & 7)) << 4));
                    LDSM4(f[(k + 1) & 1][4], f[(k + 1) & 1][5], f[(k + 1) & 1][6], f[(k + 1) & 1][7],
                          sBc + r1 * 128 + ((kb ^ (r1 & 7)) << 4));
                }
                const uint32_t* b = f[k & 1];
                MMA16816H(acc[0][0][0][0], acc[0][0][0][1], Af[0][k], b[0], b[1]);
                MMA16816H(acc[0][0][1][0], acc[0][0][1][1], Af[0][k], b[2], b[3]);
                MMA16816H(acc[0][1][0][0], acc[0][1][0][1], Af[1][k], b[0], b[1]);
                MMA16816H(acc[0][1][1][0], acc[0][1][1][1], Af[1][k], b[2], b[3]);
                MMA16816H(acc[1][0][0][0], acc[1][0][0][1], Af[0][k], b[4], b[5]);
                MMA16816H(acc[1][0][1][0], acc[1][0][1][1], Af[0][k], b[6], b[7]);
                MMA16816H(acc[1][1][0][0], acc[1][1][0][1], Af[1][k], b[4], b[5]);
                MMA16816H(acc[1][1][1][0], acc[1][1][1][1], Af[1][k], b[6], b[7]);
            }

#pragma unroll
            for (int pi = 0; pi < 2; pi++)
#pragma unroll
                for (int mt = 0; mt < 2; mt++)
#pragma unroll
                    for (int nt = 0; nt < 2; nt++) {
                        kmax[mt][0] = __hmax2(kmax[mt][0], u2h(acc[pi][mt][nt][0]));
                        kmax[mt][1] = __hmax2(kmax[mt][1], u2h(acc[pi][mt][nt][1]));
                    }
        }

        MBARRIER_ARRIVE(emptyB + fs * 8);    // slot reusable
        if (++fs == RING) { fs = 0; fp ^= 1; }
    }

    // ---- reduce across 4 tc lanes; publish approx min d^2 ----
#pragma unroll
    for (int mt = 0; mt < 2; mt++)
#pragma unroll
        for (int h = 0; h < 2; h++) {
            uint32_t k = h2u(kmax[mt][h]);
            k = h2u(__hmax2(u2h(k), u2h(__shfl_xor_sync(0xFFFFFFFFu, k, 1))));
            k = h2u(__hmax2(u2h(k), u2h(__shfl_xor_sync(0xFFFFFFFFu, k, 2))));
            float x2row = __shfl_sync(0xFFFFFFFFu, x2, mt * 16 + h * 8 + g);
            if (tc == 0) {
                __half2 v = u2h(k);
                float smax = fmaxf(__half2float(__low2half(v)), __half2float(__high2half(v)));
                sD2[mbw + mt * 16 + h * 8 + g] = fmaf(smax, -2.f, x2row);
            }
        }
    asm volatile("bar.sync 1, 128;" ::: "memory");   // consumer threads only

    // ---- fused finalize: thread t owns row t ----
    {
        const int row = blockIdx.x * MT + t;
        float d2a = sD2[t];
        float res = -1.0f;
        if (d2a <= 4.0f) {       // fp16 error << 3.9; rescue: exact fp32 rescan
            const float* xr = x + (size_t)row * D;
            float best = 3.4e38f;
            int   bi = 0;
#pragma unroll 1
            for (int m = 0; m < M; m++) {
                const float* c = codes + (size_t)m * D;
                float s = 0.f;
#pragma unroll 4
                for (int i = 0; i < D; i++) {
                    float dd = __ldg(xr + i) - __ldg(c + i);
                    s = fmaf(dd, dd, s);
                }
                if (s < best) { best = s; bi = m; }
            }
            if (best <= 0.1f) res = (float)bi;
        }
        out[row] = res;
    }
}

extern "C" void kernel_launch(void* const* d_in, const int* in_sizes, int n_in,
                              void* d_out, int out_size) {
    const float* x     = (const float*)d_in[0];
    const float* codes = (const float*)d_in[1];
    float*       out   = (float*)d_out;

    const int M     = in_sizes[1] / D;     // 4096
    const int nRows = in_sizes[0] / D;     // 65536

    static bool attr = false;
    if (!attr) {
        cudaFuncSetAttribute(nn_mma_kernel,
                             cudaFuncAttributeMaxDynamicSharedMemorySize, SMEM_TOTAL);
        attr = true;
    }

    prep_kernel<<<(M * 16) / 256, 256>>>(codes, M);
    nn_mma_kernel<<<nRows / MT, TPB, SMEM_TOTAL>>>(x, codes, out, M);
}